// round 4
// baseline (speedup 1.0000x reference)
#include <cuda_runtime.h>
#include <cstdint>

#define DIMS   256
#define NP     100
#define TOPK   5
#define ROWS   32                  // x rows per CTA
#define PSPLIT 2                   // p-range split groups (warp 0 / warp 1)
#define PPG    50                  // points per group
#define PBLK   5                   // register-blocked ref points
#define CH     (PSPLIT * PBLK)     // 10 points staged per step
#define STEPS  (PPG / PBLK)        // 10
#define NTHREADS (ROWS * PSPLIT)   // 64 (2 warps)

__global__ void __launch_bounds__(NTHREADS)
knn_topk_kernel(const float* __restrict__ x,
                const float* __restrict__ ref,
                float* __restrict__ out,     // indices written as float32 (__output__ dtype)
                int B)
{
    // Static shared: 32 KB (x) + 10 KB (ref chunk) + 1.25 KB (merge) = 44.3 KB < 48 KB
    __shared__ float4 xs[ROWS * 64];     // x tile, XOR-swizzled at float4 granularity
    __shared__ float4 rs[CH * 64];       // current 10 ref points, plain layout
    __shared__ float  md[ROWS * TOPK];   // merge: group-1 partial top-5 dists
    __shared__ int    mo[ROWS * TOPK];   // merge: group-1 partial top-5 indices

    const int tid  = threadIdx.x;
    const int row0 = blockIdx.x * ROWS;
    const int nrows = (B - row0) < ROWS ? (B - row0) : ROWS;

    // ---- stage x tile (swizzle: float4 column c -> c ^ (r & 7)) ----
    {
        const float4* x4 = (const float4*)x;
        for (int i = tid; i < ROWS * 64; i += NTHREADS) {
            int r = i >> 6, c = i & 63;
            if (r < nrows)
                xs[r * 64 + (c ^ (r & 7))] = x4[(size_t)(row0 + r) * 64 + c];
        }
    }

    const int r = tid & 31;        // row within tile (lane)
    const int g = tid >> 5;        // p-split group (warp id)

    const float INF = __int_as_float(0x7f800000);
    float bd[TOPK]; int bi[TOPK];
#pragma unroll
    for (int j = 0; j < TOPK; ++j) { bd[j] = INF; bi[j] = 0; }

    const float4* r4 = (const float4*)ref;

    for (int step = 0; step < STEPS; ++step) {
        __syncthreads();           // protect rs from previous step's readers
        // ---- stage 10 ref points: slot s -> global p = (s/5)*50 + step*5 + (s%5) ----
        for (int i = tid; i < CH * 64; i += NTHREADS) {
            int s = i >> 6, c = i & 63;
            int p = (s / PBLK) * PPG + step * PBLK + (s % PBLK);
            rs[i] = r4[(size_t)p * 64 + c];
        }
        __syncthreads();

        if (r < nrows) {
            float acc[PBLK][4];
#pragma unroll
            for (int pp = 0; pp < PBLK; ++pp)
#pragma unroll
                for (int k = 0; k < 4; ++k) acc[pp][k] = 0.0f;

#pragma unroll 4
            for (int j = 0; j < 64; ++j) {
                float4 xv = xs[r * 64 + (j ^ (r & 7))];
#pragma unroll
                for (int pp = 0; pp < PBLK; ++pp) {
                    float4 rv = rs[(g * PBLK + pp) * 64 + j];   // warp-uniform broadcast
                    float d0 = xv.x - rv.x;
                    float d1 = xv.y - rv.y;
                    float d2 = xv.z - rv.z;
                    float d3 = xv.w - rv.w;
                    acc[pp][0] = fmaf(d0, d0, acc[pp][0]);
                    acc[pp][1] = fmaf(d1, d1, acc[pp][1]);
                    acc[pp][2] = fmaf(d2, d2, acc[pp][2]);
                    acc[pp][3] = fmaf(d3, d3, acc[pp][3]);
                }
            }

#pragma unroll
            for (int pp = 0; pp < PBLK; ++pp) {
                float dist = (acc[pp][0] + acc[pp][1]) + (acc[pp][2] + acc[pp][3]);
                int   idx  = g * PPG + step * PBLK + pp;
                // ascending p + strict '<'  ==  lax.top_k lowest-index-first tie break
                if (dist < bd[TOPK - 1]) {
                    bd[TOPK - 1] = dist; bi[TOPK - 1] = idx;
#pragma unroll
                    for (int t = TOPK - 1; t >= 1; --t) {
                        if (bd[t] < bd[t - 1]) {
                            float tf = bd[t]; bd[t] = bd[t - 1]; bd[t - 1] = tf;
                            int   ti = bi[t]; bi[t] = bi[t - 1]; bi[t - 1] = ti;
                        }
                    }
                }
            }
        }
    }

    // ---- merge group 1 into group 0, write output ----
    __syncthreads();
    if (g == 1 && r < nrows) {
#pragma unroll
        for (int j = 0; j < TOPK; ++j) { md[r * TOPK + j] = bd[j]; mo[r * TOPK + j] = bi[j]; }
    }
    __syncthreads();

    if (g == 0 && r < nrows) {
#pragma unroll
        for (int j = 0; j < TOPK; ++j) {
            float dist = md[r * TOPK + j];
            int   idx  = mo[r * TOPK + j];
            if (dist < bd[TOPK - 1]) {
                bd[TOPK - 1] = dist; bi[TOPK - 1] = idx;
#pragma unroll
                for (int t = TOPK - 1; t >= 1; --t) {
                    if (bd[t] < bd[t - 1]) {
                        float tf = bd[t]; bd[t] = bd[t - 1]; bd[t - 1] = tf;
                        int   ti = bi[t]; bi[t] = bi[t - 1]; bi[t - 1] = ti;
                    }
                }
            }
        }
        float* o = out + (size_t)(row0 + r) * TOPK;
#pragma unroll
        for (int j = 0; j < TOPK; ++j) o[j] = (float)bi[j];   // indices as float32
    }
}

extern "C" void kernel_launch(void* const* d_in, const int* in_sizes, int n_in,
                              void* d_out, int out_size)
{
    // Robust binding: ref is the smaller buffer; B from the output size.
    const float* a = (const float*)d_in[0];
    const float* b = (const float*)d_in[1];
    const float* x   = (in_sizes[0] >= in_sizes[1]) ? a : b;
    const float* ref = (in_sizes[0] >= in_sizes[1]) ? b : a;
    int B = out_size / TOPK;                     // 16384

    float* out = (float*)d_out;                  // __output__ dtype: float32
    int grid = (B + ROWS - 1) / ROWS;            // 512
    knn_topk_kernel<<<grid, NTHREADS>>>(x, ref, out, B);
}

// round 8
// speedup vs baseline: 1.2508x; 1.2508x over previous
#include <cuda_runtime.h>
#include <cstdint>

#define DIMS     256
#define NP       100
#define TOPK     5
#define ROWS     112                 // x rows per CTA -> grid 147 = one CTA/SM, single wave
#define PSPLIT   4                   // p-range split groups
#define PPT      25                  // ref points per group
#define PBLK     5                   // register-blocked points per step (acc regs low)
#define NTHREADS (ROWS * PSPLIT)     // 448 (14 warps)

#define XS_BYTES  (ROWS * 1024)      // 114688: x tile, swizzled, 1KB row stride
#define RF_BYTES  (NP * 1024)        // 102400: negated ref, plain layout
#define SMEM_BYTES (XS_BYTES + RF_BYTES)   // 217088 B

typedef unsigned long long u64;

__device__ __forceinline__ u64 f32x2_add(u64 a, u64 b) {
    u64 r; asm("add.rn.f32x2 %0, %1, %2;" : "=l"(r) : "l"(a), "l"(b)); return r;
}
__device__ __forceinline__ u64 f32x2_fma(u64 a, u64 b, u64 c) {
    u64 r; asm("fma.rn.f32x2 %0, %1, %2, %3;" : "=l"(r) : "l"(a), "l"(b), "l"(c)); return r;
}
__device__ __forceinline__ void lds_v2u64(uint32_t addr, u64& a, u64& b) {
    asm volatile("ld.shared.v2.u64 {%0, %1}, [%2];" : "=l"(a), "=l"(b) : "r"(addr));
}
__device__ __forceinline__ float2 unpk(u64 v) {
    float2 f; asm("mov.b64 {%0, %1}, %2;" : "=f"(f.x), "=f"(f.y) : "l"(v)); return f;
}

__global__ void __launch_bounds__(NTHREADS)
knn_topk_kernel(const float* __restrict__ x,
                const float* __restrict__ ref,
                float* __restrict__ out,     // indices as float32 (__output__ dtype!)
                int B)
{
    extern __shared__ unsigned char smem[];
    const uint32_t s0 = (uint32_t)__cvta_generic_to_shared(smem);

    const int tid  = threadIdx.x;
    const int row0 = blockIdx.x * ROWS;
    const int nrows = (B - row0) < ROWS ? (B - row0) : ROWS;

    // ---- stage x tile, XOR-swizzled (float4 col c -> c ^ (r&7)) ----
    {
        const float4* x4 = (const float4*)x;
        for (int i = tid; i < ROWS * 64; i += NTHREADS) {
            int rr = i >> 6, c = i & 63;
            if (rr < nrows) {
                uint32_t off = (uint32_t)(rr * 1024) + (uint32_t)((c ^ (rr & 7)) * 16);
                *(float4*)(smem + off) = x4[(size_t)(row0 + rr) * 64 + c];
            }
        }
    }
    // ---- stage NEGATED ref (diff = add.rn.f32x2(x, -r): lane-wise identical to scalar sub) ----
    {
        const float4* r4 = (const float4*)ref;
        for (int i = tid; i < NP * 64; i += NTHREADS) {
            float4 v = r4[i];
            v.x = -v.x; v.y = -v.y; v.z = -v.z; v.w = -v.w;
            *(float4*)(smem + XS_BYTES + (uint32_t)i * 16) = v;
        }
    }
    __syncthreads();

    const int r = tid % ROWS;        // row within tile
    const int g = tid / ROWS;        // p-split group 0..3
    const int p0 = g * PPT;

    const float INF = __int_as_float(0x7f800000);
    float bd[TOPK]; int bi[TOPK];
#pragma unroll
    for (int j = 0; j < TOPK; ++j) { bd[j] = INF; bi[j] = 0; }

    if (r < nrows) {
        const uint32_t xbase = s0 + (uint32_t)(r * 1024);
        const uint32_t xorm  = (uint32_t)(r & 7) << 4;

        for (int pb = 0; pb < PPT; pb += PBLK) {
            const uint32_t rb0 = s0 + XS_BYTES + (uint32_t)((p0 + pb) * 1024);

            // Two u64 accumulators per point: lanes = component classes (0,1) and (2,3).
            // Bit-identical to the proven scalar 4-way class split of Round 4.
            u64 accA[PBLK], accB[PBLK];
#pragma unroll
            for (int pp = 0; pp < PBLK; ++pp) { accA[pp] = 0ULL; accB[pp] = 0ULL; }

#pragma unroll 4
            for (int j = 0; j < 64; ++j) {           // 64 x 16B chunks over D=256
                u64 xl, xh;
                lds_v2u64(xbase + (((uint32_t)(j * 16)) ^ xorm), xl, xh);
#pragma unroll
                for (int pp = 0; pp < PBLK; ++pp) {
                    u64 rl, rh;
                    lds_v2u64(rb0 + (uint32_t)(pp * 1024 + j * 16), rl, rh);  // broadcast
                    u64 dl = f32x2_add(xl, rl);      // (d0, d1)
                    u64 dh = f32x2_add(xh, rh);      // (d2, d3)
                    accA[pp] = f32x2_fma(dl, dl, accA[pp]);   // classes 0,1
                    accB[pp] = f32x2_fma(dh, dh, accB[pp]);   // classes 2,3
                }
            }

#pragma unroll
            for (int pp = 0; pp < PBLK; ++pp) {
                float2 a = unpk(accA[pp]);
                float2 b = unpk(accB[pp]);
                float dist = (a.x + a.y) + (b.x + b.y);   // (a0+a1)+(a2+a3): Round-4 tree
                int   idx  = p0 + pb + pp;
                // ascending p + strict '<'  ==  lax.top_k lowest-index-first tie break
                if (dist < bd[TOPK - 1]) {
                    bd[TOPK - 1] = dist; bi[TOPK - 1] = idx;
#pragma unroll
                    for (int t = TOPK - 1; t >= 1; --t) {
                        if (bd[t] < bd[t - 1]) {
                            float tf = bd[t]; bd[t] = bd[t - 1]; bd[t - 1] = tf;
                            int   ti = bi[t]; bi[t] = bi[t - 1]; bi[t - 1] = ti;
                        }
                    }
                }
            }
        }
    }

    // ---- merge 4 partial top-5 lists per row (reuse ref SMEM region) ----
    __syncthreads();
    float* mf = (float*)(smem + XS_BYTES);
    int*   mi = (int*)(smem + XS_BYTES + (PSPLIT - 1) * ROWS * TOPK * sizeof(float));

    if (g >= 1 && r < nrows) {
        int base = ((g - 1) * ROWS + r) * TOPK;
#pragma unroll
        for (int j = 0; j < TOPK; ++j) { mf[base + j] = bd[j]; mi[base + j] = bi[j]; }
    }
    __syncthreads();

    if (g == 0 && r < nrows) {
        for (int gg = 1; gg < PSPLIT; ++gg) {
            int base = ((gg - 1) * ROWS + r) * TOPK;
#pragma unroll
            for (int j = 0; j < TOPK; ++j) {
                float dist = mf[base + j];
                int   idx  = mi[base + j];
                if (dist < bd[TOPK - 1]) {
                    bd[TOPK - 1] = dist; bi[TOPK - 1] = idx;
#pragma unroll
                    for (int t = TOPK - 1; t >= 1; --t) {
                        if (bd[t] < bd[t - 1]) {
                            float tf = bd[t]; bd[t] = bd[t - 1]; bd[t - 1] = tf;
                            int   ti = bi[t]; bi[t] = bi[t - 1]; bi[t - 1] = ti;
                        }
                    }
                }
            }
        }
        float* o = out + (size_t)(row0 + r) * TOPK;
#pragma unroll
        for (int j = 0; j < TOPK; ++j) o[j] = (float)bi[j];
    }
}

extern "C" void kernel_launch(void* const* d_in, const int* in_sizes, int n_in,
                              void* d_out, int out_size)
{
    const float* a = (const float*)d_in[0];
    const float* b = (const float*)d_in[1];
    const float* x   = (in_sizes[0] >= in_sizes[1]) ? a : b;
    const float* ref = (in_sizes[0] >= in_sizes[1]) ? b : a;
    int B = out_size / TOPK;                     // 16384

    float* out = (float*)d_out;
    cudaFuncSetAttribute(knn_topk_kernel,
                         cudaFuncAttributeMaxDynamicSharedMemorySize, SMEM_BYTES);
    int grid = (B + ROWS - 1) / ROWS;            // 147 -> one CTA per SM
    knn_topk_kernel<<<grid, NTHREADS, SMEM_BYTES>>>(x, ref, out, B);
}

// round 9
// speedup vs baseline: 1.4238x; 1.1383x over previous
#include <cuda_runtime.h>
#include <cstdint>

#define TOPK     5
#define ROWS     112                 // x rows per CTA -> grid 147 = one CTA/SM, single wave
#define PSPLIT   8                   // p-range split groups -> 896 threads, 28 warps
#define PPT      13                  // points per group (8*13 = 104 = padded NP)
#define NP       100
#define NPPAD    104
#define NTHREADS (ROWS * PSPLIT)     // 896

#define XS_BYTES  (ROWS * 1024)      // 114688: x tile, swizzled, 1KB row stride
#define RF_BYTES  (NPPAD * 1024)     // 106496: negated ref (+4 pad rows of -1e18)
#define SMEM_BYTES (XS_BYTES + RF_BYTES)   // 221184 B (<= 232448 cap)

typedef unsigned long long u64;

__device__ __forceinline__ u64 f32x2_add(u64 a, u64 b) {
    u64 r; asm("add.rn.f32x2 %0, %1, %2;" : "=l"(r) : "l"(a), "l"(b)); return r;
}
__device__ __forceinline__ u64 f32x2_fma(u64 a, u64 b, u64 c) {
    u64 r; asm("fma.rn.f32x2 %0, %1, %2, %3;" : "=l"(r) : "l"(a), "l"(b), "l"(c)); return r;
}
__device__ __forceinline__ void lds_v2u64(uint32_t addr, u64& a, u64& b) {
    asm volatile("ld.shared.v2.u64 {%0, %1}, [%2];" : "=l"(a), "=l"(b) : "r"(addr));
}
__device__ __forceinline__ float2 unpk(u64 v) {
    float2 f; asm("mov.b64 {%0, %1}, %2;" : "=f"(f.x), "=f"(f.y) : "l"(v)); return f;
}

__device__ __forceinline__ void topk_insert(float dist, int idx, float* bd, int* bi) {
    // ascending p + strict '<'  ==  lax.top_k lowest-index-first tie break
    if (dist < bd[TOPK - 1]) {
        bd[TOPK - 1] = dist; bi[TOPK - 1] = idx;
#pragma unroll
        for (int t = TOPK - 1; t >= 1; --t) {
            if (bd[t] < bd[t - 1]) {
                float tf = bd[t]; bd[t] = bd[t - 1]; bd[t - 1] = tf;
                int   ti = bi[t]; bi[t] = bi[t - 1]; bi[t - 1] = ti;
            }
        }
    }
}

// Diff-square for PB points with the PROVEN bit-exact reduction tree:
// accA lanes = component classes (0,1), accB = (2,3); final (A.x+A.y)+(B.x+B.y).
template<int PB>
__device__ __forceinline__ void compute_block(
    uint32_t xbase, uint32_t xorm, uint32_t rb0, int pbase,
    float* bd, int* bi)
{
    u64 accA[PB], accB[PB];
#pragma unroll
    for (int pp = 0; pp < PB; ++pp) { accA[pp] = 0ULL; accB[pp] = 0ULL; }

#pragma unroll 4
    for (int j = 0; j < 64; ++j) {               // 64 x 16B chunks over D=256
        u64 xl, xh;
        lds_v2u64(xbase + (((uint32_t)(j * 16)) ^ xorm), xl, xh);
#pragma unroll
        for (int pp = 0; pp < PB; ++pp) {
            u64 rl, rh;
            lds_v2u64(rb0 + (uint32_t)(pp * 1024 + j * 16), rl, rh);  // broadcast
            u64 dl = f32x2_add(xl, rl);          // (d0, d1) = x + (-r)
            u64 dh = f32x2_add(xh, rh);          // (d2, d3)
            accA[pp] = f32x2_fma(dl, dl, accA[pp]);
            accB[pp] = f32x2_fma(dh, dh, accB[pp]);
        }
    }

#pragma unroll
    for (int pp = 0; pp < PB; ++pp) {
        float2 a = unpk(accA[pp]);
        float2 b = unpk(accB[pp]);
        float dist = (a.x + a.y) + (b.x + b.y);  // Round-4 exact tree
        topk_insert(dist, pbase + pp, bd, bi);
    }
}

__global__ void __launch_bounds__(NTHREADS)
knn_topk_kernel(const float* __restrict__ x,
                const float* __restrict__ ref,
                float* __restrict__ out,     // indices as float32 (__output__ dtype!)
                int B)
{
    extern __shared__ unsigned char smem[];
    const uint32_t s0 = (uint32_t)__cvta_generic_to_shared(smem);

    const int tid  = threadIdx.x;
    const int row0 = blockIdx.x * ROWS;
    const int nrows = (B - row0) < ROWS ? (B - row0) : ROWS;

    // ---- stage x tile, XOR-swizzled (float4 col c -> c ^ (r&7)) ----
    {
        const float4* x4 = (const float4*)x;
        for (int i = tid; i < ROWS * 64; i += NTHREADS) {
            int rr = i >> 6, c = i & 63;
            if (rr < nrows) {
                uint32_t off = (uint32_t)(rr * 1024) + (uint32_t)((c ^ (rr & 7)) * 16);
                *(float4*)(smem + off) = x4[(size_t)(row0 + rr) * 64 + c];
            }
        }
    }
    // ---- stage NEGATED ref; pad rows 100..103 with -1e18 (never in top-k) ----
    {
        const float4* r4 = (const float4*)ref;
        for (int i = tid; i < NPPAD * 64; i += NTHREADS) {
            int p = i >> 6, c = i & 63;
            float4 v;
            if (p < NP) {
                v = r4[p * 64 + c];
                v.x = -v.x; v.y = -v.y; v.z = -v.z; v.w = -v.w;
            } else {
                v.x = v.y = v.z = v.w = -1e18f;
            }
            *(float4*)(smem + XS_BYTES + (uint32_t)(p * 1024 + c * 16)) = v;
        }
    }
    __syncthreads();

    const int r = tid % ROWS;        // row within tile
    const int g = tid / ROWS;        // p-split group 0..7
    const int p0 = g * PPT;

    const float INF = __int_as_float(0x7f800000);
    float bd[TOPK]; int bi[TOPK];
#pragma unroll
    for (int j = 0; j < TOPK; ++j) { bd[j] = INF; bi[j] = 0; }

    if (r < nrows) {
        const uint32_t xbase = s0 + (uint32_t)(r * 1024);
        const uint32_t xorm  = (uint32_t)(r & 7) << 4;
        const uint32_t rb0   = s0 + XS_BYTES + (uint32_t)(p0 * 1024);

        compute_block<7>(xbase, xorm, rb0,            p0,     bd, bi);
        compute_block<6>(xbase, xorm, rb0 + 7 * 1024, p0 + 7, bd, bi);
    }

    // ---- merge 8 partial top-5 lists per row (reuse ref SMEM region) ----
    __syncthreads();
    float* mf = (float*)(smem + XS_BYTES);
    int*   mi = (int*)(smem + XS_BYTES + (PSPLIT - 1) * ROWS * TOPK * sizeof(float));

    if (g >= 1 && r < nrows) {
        int base = ((g - 1) * ROWS + r) * TOPK;
#pragma unroll
        for (int j = 0; j < TOPK; ++j) { mf[base + j] = bd[j]; mi[base + j] = bi[j]; }
    }
    __syncthreads();

    if (g == 0 && r < nrows) {
        for (int gg = 1; gg < PSPLIT; ++gg) {
            int base = ((gg - 1) * ROWS + r) * TOPK;
#pragma unroll
            for (int j = 0; j < TOPK; ++j)
                topk_insert(mf[base + j], mi[base + j], bd, bi);
        }
        float* o = out + (size_t)(row0 + r) * TOPK;
#pragma unroll
        for (int j = 0; j < TOPK; ++j) o[j] = (float)bi[j];
    }
}

extern "C" void kernel_launch(void* const* d_in, const int* in_sizes, int n_in,
                              void* d_out, int out_size)
{
    const float* a = (const float*)d_in[0];
    const float* b = (const float*)d_in[1];
    const float* x   = (in_sizes[0] >= in_sizes[1]) ? a : b;
    const float* ref = (in_sizes[0] >= in_sizes[1]) ? b : a;
    int B = out_size / TOPK;                     // 16384

    float* out = (float*)d_out;
    cudaFuncSetAttribute(knn_topk_kernel,
                         cudaFuncAttributeMaxDynamicSharedMemorySize, SMEM_BYTES);
    int grid = (B + ROWS - 1) / ROWS;            // 147 -> one CTA per SM
    knn_topk_kernel<<<grid, NTHREADS, SMEM_BYTES>>>(x, ref, out, B);
}